// round 2
// baseline (speedup 1.0000x reference)
#include <cuda_runtime.h>
#include <cstdint>

#define NN 50000
#define NE 200000
#define HH 512
#define G3 1536

// ---------------- device scratch (static, no allocation) ----------------
__device__ int g_is64;
__device__ int g_src[NE];
__device__ int g_dst[NE];
__device__ int g_inp[NN];
__device__ int g_rowptr[NN + 1];
__device__ int g_cursor[NN];
__device__ int g_csr[NE];
__device__ float g_x0[(size_t)NN * HH];
__device__ float g_x1[(size_t)NN * HH];
__device__ float g_S[(size_t)NN * HH];
__device__ float g_Wp[2][(size_t)HH * G3];

// ---------------- helpers ----------------
__device__ __forceinline__ uint32_t f2tf(float f) {
    uint32_t u;
    asm("cvt.rna.tf32.f32 %0, %1;" : "=r"(u) : "f"(f));
    return u;
}

__device__ __forceinline__ void mma8(float* c, uint32_t a0, uint32_t a1,
                                     uint32_t a2, uint32_t a3,
                                     uint32_t b0, uint32_t b1) {
    asm volatile(
        "mma.sync.aligned.m16n8k8.row.col.f32.tf32.tf32.f32 "
        "{%0,%1,%2,%3},{%4,%5,%6,%7},{%8,%9},{%0,%1,%2,%3};"
        : "+f"(c[0]), "+f"(c[1]), "+f"(c[2]), "+f"(c[3])
        : "r"(a0), "r"(a1), "r"(a2), "r"(a3), "r"(b0), "r"(b1));
}

__device__ __forceinline__ float sigm(float v) { return 1.f / (1.f + __expf(-v)); }
__device__ __forceinline__ float tanh_fast(float v) { return 1.f - 2.f / (__expf(2.f * v) + 1.f); }

// ---------------- dtype detection: int64 vs int32 indices ----------------
__global__ void k_detect(const int* __restrict__ A) {
    __shared__ int nz;
    if (threadIdx.x == 0) nz = 0;
    __syncthreads();
    // If data is int64 (values in [0,50000)), every high word is 0.
    if (A[2 * threadIdx.x + 1] != 0) atomicOr(&nz, 1);
    __syncthreads();
    if (threadIdx.x == 0) g_is64 = (nz == 0) ? 1 : 0;
}

// convert edges + inputs to int32 scratch; zero rowptr
__global__ void k_prep(const void* __restrict__ Ab, const void* __restrict__ Ib) {
    int idx = blockIdx.x * blockDim.x + threadIdx.x;
    int is64 = g_is64;
    if (idx < 2 * NE) {
        long long v = is64 ? ((const long long*)Ab)[idx]
                           : (long long)((const int*)Ab)[idx];
        if (idx < NE) g_src[idx] = (int)v;
        else          g_dst[idx - NE] = (int)v;
    } else if (idx < 2 * NE + NN) {
        int i = idx - 2 * NE;
        long long v = is64 ? ((const long long*)Ib)[i]
                           : (long long)((const int*)Ib)[i];
        g_inp[i] = (int)v;
    } else if (idx < 2 * NE + NN + NN + 1) {
        g_rowptr[idx - 2 * NE - NN] = 0;
    }
}

// x0 = emb[inputs]
__global__ void k_gx0(const float* __restrict__ emb) {
    int i = blockIdx.x * blockDim.x + threadIdx.x;  // over NN*128 float4
    if (i < NN * (HH / 4)) {
        int row = i >> 7, c = i & 127;
        ((float4*)g_x0)[i] =
            ((const float4*)(emb + (size_t)g_inp[row] * HH))[c];
    }
}

// ---------------- CSR build ----------------
__global__ void k_hist() {
    int e = blockIdx.x * blockDim.x + threadIdx.x;
    if (e < NE) atomicAdd(&g_rowptr[g_dst[e] + 1], 1);
}

__global__ void k_scan() {
    __shared__ int sh[1024];
    int t = threadIdx.x;
    int carry = 0;
    for (int base = 0; base < NN; base += 1024) {
        int i = base + t;
        int v = (i < NN) ? g_rowptr[i + 1] : 0;
        sh[t] = v;
        __syncthreads();
        for (int off = 1; off < 1024; off <<= 1) {
            int u = (t >= off) ? sh[t - off] : 0;
            __syncthreads();
            sh[t] += u;
            __syncthreads();
        }
        if (i < NN) g_rowptr[i + 1] = carry + sh[t];
        carry += sh[1023];
        __syncthreads();
    }
}

__global__ void k_cur() {
    int i = blockIdx.x * blockDim.x + threadIdx.x;
    if (i < NN) g_cursor[i] = g_rowptr[i];
}

__global__ void k_fill() {
    int e = blockIdx.x * blockDim.x + threadIdx.x;
    if (e < NE) {
        int p = atomicAdd(&g_cursor[g_dst[e]], 1);
        g_csr[p] = g_src[e];
    }
}

// S[node] = sum over in-edges of x[src]   (one block per node, 128 thr = 512 floats)
__global__ void k_gsum(int xsel) {
    const float* __restrict__ X = xsel ? g_x1 : g_x0;
    int node = blockIdx.x;
    int beg = g_rowptr[node], end = g_rowptr[node + 1];
    float4 acc = make_float4(0.f, 0.f, 0.f, 0.f);
    for (int j = beg; j < end; j++) {
        int s = g_csr[j];
        float4 v = *(const float4*)(X + (size_t)s * HH + threadIdx.x * 4);
        acc.x += v.x; acc.y += v.y; acc.z += v.z; acc.w += v.w;
    }
    *(float4*)(g_S + (size_t)node * HH + threadIdx.x * 4) = acc;
}

// ---------------- Wp[l] = W_l @ w_ih^T   [512,1536], tf32 mma ----------------
__global__ void __launch_bounds__(256) k_wp(const float* __restrict__ W,
                                            const float* __restrict__ Wih,
                                            int layer) {
    float* __restrict__ C = g_Wp[layer];
    __shared__ __align__(16) uint32_t As[64][36];
    __shared__ __align__(16) uint32_t Bs[32][36];  // [col][k]
    const int tid = threadIdx.x;
    const int lane = tid & 31, wid = tid >> 5;
    const int wm = wid & 3, wn = wid >> 2;
    const int g8 = lane >> 2, t4 = lane & 3;
    const int i0 = blockIdx.y * 64;   // k-rows of Wp
    const int c0 = blockIdx.x * 32;   // j-cols of Wp
    float acc[8];
#pragma unroll
    for (int b = 0; b < 8; b++) acc[b] = 0.f;

    for (int kt = 0; kt < 16; kt++) {
        const int kk0 = kt * 32;
        __syncthreads();
#pragma unroll
        for (int r2 = 0; r2 < 2; r2++) {  // A: 64x32 = 512 f4
            int v = tid + 256 * r2;
            int row = v >> 3, c4 = v & 7;
            float4 a = *(const float4*)(W + (size_t)(i0 + row) * HH + kk0 + c4 * 4);
            uint4 u; u.x = f2tf(a.x); u.y = f2tf(a.y); u.z = f2tf(a.z); u.w = f2tf(a.w);
            *(uint4*)&As[row][c4 * 4] = u;
        }
        {  // B: 32x32 = 256 f4
            int col = tid >> 3, k4 = tid & 7;
            float4 b = *(const float4*)(Wih + (size_t)(c0 + col) * HH + kk0 + k4 * 4);
            uint4 u; u.x = f2tf(b.x); u.y = f2tf(b.y); u.z = f2tf(b.z); u.w = f2tf(b.w);
            *(uint4*)&Bs[col][k4 * 4] = u;
        }
        __syncthreads();
#pragma unroll
        for (int ks = 0; ks < 4; ks++) {
            const int kb = ks * 8;
            uint32_t a0 = As[wm * 16 + g8][kb + t4];
            uint32_t a1 = As[wm * 16 + g8 + 8][kb + t4];
            uint32_t a2 = As[wm * 16 + g8][kb + t4 + 4];
            uint32_t a3 = As[wm * 16 + g8 + 8][kb + t4 + 4];
#pragma unroll
            for (int nt = 0; nt < 2; nt++) {
                int nc = wn * 16 + nt * 8 + g8;
                uint32_t b0 = Bs[nc][kb + t4];
                uint32_t b1 = Bs[nc][kb + t4 + 4];
                mma8(acc + nt * 4, a0, a1, a2, a3, b0, b1);
            }
        }
    }
#pragma unroll
    for (int nt = 0; nt < 2; nt++)
#pragma unroll
        for (int j = 0; j < 4; j++) {
            int row = i0 + wm * 16 + g8 + ((j >> 1) << 3);
            int col = c0 + wn * 16 + nt * 8 + t4 * 2 + (j & 1);
            C[(size_t)row * G3 + col] = acc[nt * 4 + j];
        }
}

// ---------------- fused GEMM + GRU ----------------
// gi_{r,z,n} = S @ Wp ; gh_{r,z,n} = X @ w_hh^T ; epilogue -> out
__global__ void __launch_bounds__(512) k_fused(int layer, int xsel, int final_out,
                                               float* __restrict__ dout,
                                               const float* __restrict__ Whh,
                                               const float* __restrict__ bih,
                                               const float* __restrict__ bhh) {
    const float* __restrict__ X = xsel ? g_x1 : g_x0;
    const float* __restrict__ Wp = g_Wp[layer];
    float* __restrict__ out = final_out ? dout : g_x1;

    __shared__ __align__(16) uint32_t As[128][36];
    __shared__ __align__(16) uint32_t Bs[3][32][36];  // p0: [g][k][col], p1: [g][col][k]

    const int tid = threadIdx.x;
    const int lane = tid & 31, wid = tid >> 5;
    const int wm = wid & 7, wn = wid >> 3;
    const int g8 = lane >> 2, t4 = lane & 3;
    const int i0 = blockIdx.y * 128;
    const int c0 = blockIdx.x * 32;

    float acc[6][8];
#pragma unroll
    for (int a = 0; a < 6; a++)
#pragma unroll
        for (int b = 0; b < 8; b++) acc[a][b] = 0.f;

#pragma unroll
    for (int p = 0; p < 2; p++) {
        const float* __restrict__ Ap = p ? X : g_S;
        for (int kt = 0; kt < 16; kt++) {
            const int kk0 = kt * 32;
            __syncthreads();
            // A tile: 128x32 = 1024 f4
#pragma unroll
            for (int r2 = 0; r2 < 2; r2++) {
                int v = tid + 512 * r2;
                int row = v >> 3, c4 = v & 7;
                int gi = i0 + row;
                float4 a = make_float4(0.f, 0.f, 0.f, 0.f);
                if (gi < NN) a = *(const float4*)(Ap + (size_t)gi * HH + kk0 + c4 * 4);
                uint4 u; u.x = f2tf(a.x); u.y = f2tf(a.y); u.z = f2tf(a.z); u.w = f2tf(a.w);
                *(uint4*)&As[row][c4 * 4] = u;
            }
            // B tiles: 3 gates x 32 x 32 = 768 f4
            for (int v = tid; v < 768; v += 512) {
                int g = v >> 8, w = v & 255;
                if (p == 0) {
                    int k = w >> 3, c4 = w & 7;
                    float4 b = *(const float4*)(Wp + (size_t)(kk0 + k) * G3 + g * HH + c0 + c4 * 4);
                    uint4 u; u.x = f2tf(b.x); u.y = f2tf(b.y); u.z = f2tf(b.z); u.w = f2tf(b.w);
                    *(uint4*)&Bs[g][k][c4 * 4] = u;
                } else {
                    int col = w >> 3, k4 = w & 7;
                    float4 b = *(const float4*)(Whh + (size_t)(g * HH + c0 + col) * HH + kk0 + k4 * 4);
                    uint4 u; u.x = f2tf(b.x); u.y = f2tf(b.y); u.z = f2tf(b.z); u.w = f2tf(b.w);
                    *(uint4*)&Bs[g][col][k4 * 4] = u;
                }
            }
            __syncthreads();
#pragma unroll
            for (int ks = 0; ks < 4; ks++) {
                const int kb = ks * 8;
                uint32_t a0 = As[wm * 16 + g8][kb + t4];
                uint32_t a1 = As[wm * 16 + g8 + 8][kb + t4];
                uint32_t a2 = As[wm * 16 + g8][kb + t4 + 4];
                uint32_t a3 = As[wm * 16 + g8 + 8][kb + t4 + 4];
#pragma unroll
                for (int g = 0; g < 3; g++) {
#pragma unroll
                    for (int nt = 0; nt < 2; nt++) {
                        int nc = wn * 16 + nt * 8 + g8;
                        uint32_t b0, b1;
                        if (p == 0) {
                            b0 = Bs[g][kb + t4][nc];
                            b1 = Bs[g][kb + t4 + 4][nc];
                        } else {
                            b0 = Bs[g][nc][kb + t4];
                            b1 = Bs[g][nc][kb + t4 + 4];
                        }
                        mma8(acc[3 * p + g] + nt * 4, a0, a1, a2, a3, b0, b1);
                    }
                }
            }
        }
    }

    // epilogue: GRU gates
#pragma unroll
    for (int nt = 0; nt < 2; nt++)
#pragma unroll
        for (int j = 0; j < 4; j++) {
            int row = i0 + wm * 16 + g8 + ((j >> 1) << 3);
            int col = c0 + wn * 16 + nt * 8 + t4 * 2 + (j & 1);
            if (row < NN) {
                int q = nt * 4 + j;
                float vr = acc[0][q] + __ldg(&bih[col])          + acc[3][q] + __ldg(&bhh[col]);
                float vz = acc[1][q] + __ldg(&bih[col + HH])     + acc[4][q] + __ldg(&bhh[col + HH]);
                float r = sigm(vr);
                float z = sigm(vz);
                float in_ = acc[2][q] + __ldg(&bih[col + 2 * HH]);
                float hn  = acc[5][q] + __ldg(&bhh[col + 2 * HH]);
                float n = tanh_fast(in_ + r * hn);
                float h = X[(size_t)row * HH + col];
                out[(size_t)row * HH + col] = (1.f - z) * n + z * h;
            }
        }
}

// ---------------- launch ----------------
extern "C" void kernel_launch(void* const* d_in, const int* in_sizes, int n_in,
                              void* d_out, int out_size) {
    const void* inputs = d_in[0];
    const void* A      = d_in[1];
    const float* emb    = (const float*)d_in[2];
    const float* weight = (const float*)d_in[3];
    const float* w_ih   = (const float*)d_in[4];
    const float* w_hh   = (const float*)d_in[5];
    const float* b_ih   = (const float*)d_in[6];
    const float* b_hh   = (const float*)d_in[7];
    float* out = (float*)d_out;

    k_detect<<<1, 128>>>((const int*)A);
    int T = 2 * NE + NN + NN + 1;
    k_prep<<<(T + 255) / 256, 256>>>(A, inputs);
    k_gx0<<<(NN * (HH / 4) + 255) / 256, 256>>>(emb);
    k_hist<<<(NE + 255) / 256, 256>>>();
    k_scan<<<1, 1024>>>();
    k_cur<<<(NN + 255) / 256, 256>>>();
    k_fill<<<(NE + 255) / 256, 256>>>();
    for (int l = 0; l < 2; l++)
        k_wp<<<dim3(G3 / 32, HH / 64), 256>>>(weight + (size_t)l * HH * HH, w_ih, l);
    for (int l = 0; l < 2; l++) {
        k_gsum<<<NN, 128>>>(l);
        k_fused<<<dim3(HH / 32, (NN + 127) / 128), 512>>>(
            l, l, (l == 1) ? 1 : 0, out, w_hh, b_ih, b_hh);
    }
}

// round 3
// speedup vs baseline: 1.0010x; 1.0010x over previous
#include <cuda_runtime.h>
#include <cstdint>

#define NN 50000
#define NE 200000
#define HH 512
#define G3 1536

// ---------------- device scratch (static, no allocation) ----------------
__device__ int g_is64;
__device__ int g_src[NE];
__device__ int g_dst[NE];
__device__ int g_inp[NN];
__device__ int g_rowptr[NN + 1];
__device__ int g_cursor[NN];
__device__ int g_csr[NE];
__device__ float g_x0[(size_t)NN * HH];
__device__ float g_x1[(size_t)NN * HH];
__device__ float g_S[(size_t)NN * HH];
__device__ float g_Wp[2][(size_t)HH * G3];

// ---------------- helpers ----------------
__device__ __forceinline__ uint32_t f2tf(float f) {
    uint32_t u;
    asm("cvt.rna.tf32.f32 %0, %1;" : "=r"(u) : "f"(f));
    return u;
}

__device__ __forceinline__ void mma8(float* c, uint32_t a0, uint32_t a1,
                                     uint32_t a2, uint32_t a3,
                                     uint32_t b0, uint32_t b1) {
    asm volatile(
        "mma.sync.aligned.m16n8k8.row.col.f32.tf32.tf32.f32 "
        "{%0,%1,%2,%3},{%4,%5,%6,%7},{%8,%9},{%0,%1,%2,%3};"
        : "+f"(c[0]), "+f"(c[1]), "+f"(c[2]), "+f"(c[3])
        : "r"(a0), "r"(a1), "r"(a2), "r"(a3), "r"(b0), "r"(b1));
}

__device__ __forceinline__ float sigm(float v) { return 1.f / (1.f + __expf(-v)); }
__device__ __forceinline__ float tanh_fast(float v) { return 1.f - 2.f / (__expf(2.f * v) + 1.f); }

// ---------------- dtype detection: int64 vs int32 indices ----------------
__global__ void k_detect(const int* __restrict__ A) {
    __shared__ int nz;
    if (threadIdx.x == 0) nz = 0;
    __syncthreads();
    // If data is int64 (values in [0,50000)), every high word is 0.
    if (A[2 * threadIdx.x + 1] != 0) atomicOr(&nz, 1);
    __syncthreads();
    if (threadIdx.x == 0) g_is64 = (nz == 0) ? 1 : 0;
}

// convert edges + inputs to int32 scratch; zero rowptr
__global__ void k_prep(const void* __restrict__ Ab, const void* __restrict__ Ib) {
    int idx = blockIdx.x * blockDim.x + threadIdx.x;
    int is64 = g_is64;
    if (idx < 2 * NE) {
        long long v = is64 ? ((const long long*)Ab)[idx]
                           : (long long)((const int*)Ab)[idx];
        if (idx < NE) g_src[idx] = (int)v;
        else          g_dst[idx - NE] = (int)v;
    } else if (idx < 2 * NE + NN) {
        int i = idx - 2 * NE;
        long long v = is64 ? ((const long long*)Ib)[i]
                           : (long long)((const int*)Ib)[i];
        g_inp[i] = (int)v;
    } else if (idx < 2 * NE + NN + NN + 1) {
        g_rowptr[idx - 2 * NE - NN] = 0;
    }
}

// x0 = emb[inputs]
__global__ void k_gx0(const float* __restrict__ emb) {
    int i = blockIdx.x * blockDim.x + threadIdx.x;  // over NN*128 float4
    if (i < NN * (HH / 4)) {
        int row = i >> 7, c = i & 127;
        ((float4*)g_x0)[i] =
            ((const float4*)(emb + (size_t)g_inp[row] * HH))[c];
    }
}

// ---------------- CSR build ----------------
__global__ void k_hist() {
    int e = blockIdx.x * blockDim.x + threadIdx.x;
    if (e < NE) atomicAdd(&g_rowptr[g_dst[e] + 1], 1);
}

__global__ void k_scan() {
    __shared__ int sh[1024];
    int t = threadIdx.x;
    int carry = 0;
    for (int base = 0; base < NN; base += 1024) {
        int i = base + t;
        int v = (i < NN) ? g_rowptr[i + 1] : 0;
        sh[t] = v;
        __syncthreads();
        for (int off = 1; off < 1024; off <<= 1) {
            int u = (t >= off) ? sh[t - off] : 0;
            __syncthreads();
            sh[t] += u;
            __syncthreads();
        }
        if (i < NN) g_rowptr[i + 1] = carry + sh[t];
        carry += sh[1023];
        __syncthreads();
    }
}

__global__ void k_cur() {
    int i = blockIdx.x * blockDim.x + threadIdx.x;
    if (i < NN) g_cursor[i] = g_rowptr[i];
}

__global__ void k_fill() {
    int e = blockIdx.x * blockDim.x + threadIdx.x;
    if (e < NE) {
        int p = atomicAdd(&g_cursor[g_dst[e]], 1);
        g_csr[p] = g_src[e];
    }
}

// S[node] = sum over in-edges of x[src]   (one block per node, 128 thr = 512 floats)
__global__ void k_gsum(int xsel) {
    const float* __restrict__ X = xsel ? g_x1 : g_x0;
    int node = blockIdx.x;
    int beg = g_rowptr[node], end = g_rowptr[node + 1];
    float4 acc = make_float4(0.f, 0.f, 0.f, 0.f);
    for (int j = beg; j < end; j++) {
        int s = g_csr[j];
        float4 v = *(const float4*)(X + (size_t)s * HH + threadIdx.x * 4);
        acc.x += v.x; acc.y += v.y; acc.z += v.z; acc.w += v.w;
    }
    *(float4*)(g_S + (size_t)node * HH + threadIdx.x * 4) = acc;
}

// ---------------- Wp[l] = W_l @ w_ih^T   [512,1536], tf32 mma ----------------
__global__ void __launch_bounds__(256) k_wp(const float* __restrict__ W,
                                            const float* __restrict__ Wih,
                                            int layer) {
    float* __restrict__ C = g_Wp[layer];
    __shared__ __align__(16) uint32_t As[64][36];
    __shared__ __align__(16) uint32_t Bs[32][36];  // [col][k]
    const int tid = threadIdx.x;
    const int lane = tid & 31, wid = tid >> 5;
    const int wm = wid & 3, wn = wid >> 2;
    const int g8 = lane >> 2, t4 = lane & 3;
    const int i0 = blockIdx.y * 64;   // k-rows of Wp
    const int c0 = blockIdx.x * 32;   // j-cols of Wp
    float acc[8];
#pragma unroll
    for (int b = 0; b < 8; b++) acc[b] = 0.f;

    for (int kt = 0; kt < 16; kt++) {
        const int kk0 = kt * 32;
        __syncthreads();
#pragma unroll
        for (int r2 = 0; r2 < 2; r2++) {  // A: 64x32 = 512 f4
            int v = tid + 256 * r2;
            int row = v >> 3, c4 = v & 7;
            float4 a = *(const float4*)(W + (size_t)(i0 + row) * HH + kk0 + c4 * 4);
            uint4 u; u.x = f2tf(a.x); u.y = f2tf(a.y); u.z = f2tf(a.z); u.w = f2tf(a.w);
            *(uint4*)&As[row][c4 * 4] = u;
        }
        {  // B: 32x32 = 256 f4
            int col = tid >> 3, k4 = tid & 7;
            float4 b = *(const float4*)(Wih + (size_t)(c0 + col) * HH + kk0 + k4 * 4);
            uint4 u; u.x = f2tf(b.x); u.y = f2tf(b.y); u.z = f2tf(b.z); u.w = f2tf(b.w);
            *(uint4*)&Bs[col][k4 * 4] = u;
        }
        __syncthreads();
#pragma unroll
        for (int ks = 0; ks < 4; ks++) {
            const int kb = ks * 8;
            uint32_t a0 = As[wm * 16 + g8][kb + t4];
            uint32_t a1 = As[wm * 16 + g8 + 8][kb + t4];
            uint32_t a2 = As[wm * 16 + g8][kb + t4 + 4];
            uint32_t a3 = As[wm * 16 + g8 + 8][kb + t4 + 4];
#pragma unroll
            for (int nt = 0; nt < 2; nt++) {
                int nc = wn * 16 + nt * 8 + g8;
                uint32_t b0 = Bs[nc][kb + t4];
                uint32_t b1 = Bs[nc][kb + t4 + 4];
                mma8(acc + nt * 4, a0, a1, a2, a3, b0, b1);
            }
        }
    }
#pragma unroll
    for (int nt = 0; nt < 2; nt++)
#pragma unroll
        for (int j = 0; j < 4; j++) {
            int row = i0 + wm * 16 + g8 + ((j >> 1) << 3);
            int col = c0 + wn * 16 + nt * 8 + t4 * 2 + (j & 1);
            C[(size_t)row * G3 + col] = acc[nt * 4 + j];
        }
}

// ---------------- fused GEMM + GRU ----------------
// gi_{r,z,n} = S @ Wp ; gh_{r,z,n} = X @ w_hh^T ; epilogue -> out
__global__ void __launch_bounds__(512) k_fused(int layer, int xsel, int final_out,
                                               float* __restrict__ dout,
                                               const float* __restrict__ Whh,
                                               const float* __restrict__ bih,
                                               const float* __restrict__ bhh) {
    const float* __restrict__ X = xsel ? g_x1 : g_x0;
    const float* __restrict__ Wp = g_Wp[layer];
    float* __restrict__ out = final_out ? dout : g_x1;

    __shared__ __align__(16) uint32_t As[128][36];
    __shared__ __align__(16) uint32_t Bs[3][32][36];  // p0: [g][k][col], p1: [g][col][k]

    const int tid = threadIdx.x;
    const int lane = tid & 31, wid = tid >> 5;
    const int wm = wid & 7, wn = wid >> 3;
    const int g8 = lane >> 2, t4 = lane & 3;
    const int i0 = blockIdx.y * 128;
    const int c0 = blockIdx.x * 32;

    float acc[6][8];
#pragma unroll
    for (int a = 0; a < 6; a++)
#pragma unroll
        for (int b = 0; b < 8; b++) acc[a][b] = 0.f;

#pragma unroll
    for (int p = 0; p < 2; p++) {
        const float* __restrict__ Ap = p ? X : g_S;
        for (int kt = 0; kt < 16; kt++) {
            const int kk0 = kt * 32;
            __syncthreads();
            // A tile: 128x32 = 1024 f4
#pragma unroll
            for (int r2 = 0; r2 < 2; r2++) {
                int v = tid + 512 * r2;
                int row = v >> 3, c4 = v & 7;
                int gi = i0 + row;
                float4 a = make_float4(0.f, 0.f, 0.f, 0.f);
                if (gi < NN) a = *(const float4*)(Ap + (size_t)gi * HH + kk0 + c4 * 4);
                uint4 u; u.x = f2tf(a.x); u.y = f2tf(a.y); u.z = f2tf(a.z); u.w = f2tf(a.w);
                *(uint4*)&As[row][c4 * 4] = u;
            }
            // B tiles: 3 gates x 32 x 32 = 768 f4
            for (int v = tid; v < 768; v += 512) {
                int g = v >> 8, w = v & 255;
                if (p == 0) {
                    int k = w >> 3, c4 = w & 7;
                    float4 b = *(const float4*)(Wp + (size_t)(kk0 + k) * G3 + g * HH + c0 + c4 * 4);
                    uint4 u; u.x = f2tf(b.x); u.y = f2tf(b.y); u.z = f2tf(b.z); u.w = f2tf(b.w);
                    *(uint4*)&Bs[g][k][c4 * 4] = u;
                } else {
                    int col = w >> 3, k4 = w & 7;
                    float4 b = *(const float4*)(Whh + (size_t)(g * HH + c0 + col) * HH + kk0 + k4 * 4);
                    uint4 u; u.x = f2tf(b.x); u.y = f2tf(b.y); u.z = f2tf(b.z); u.w = f2tf(b.w);
                    *(uint4*)&Bs[g][col][k4 * 4] = u;
                }
            }
            __syncthreads();
#pragma unroll
            for (int ks = 0; ks < 4; ks++) {
                const int kb = ks * 8;
                uint32_t a0 = As[wm * 16 + g8][kb + t4];
                uint32_t a1 = As[wm * 16 + g8 + 8][kb + t4];
                uint32_t a2 = As[wm * 16 + g8][kb + t4 + 4];
                uint32_t a3 = As[wm * 16 + g8 + 8][kb + t4 + 4];
#pragma unroll
                for (int g = 0; g < 3; g++) {
#pragma unroll
                    for (int nt = 0; nt < 2; nt++) {
                        int nc = wn * 16 + nt * 8 + g8;
                        uint32_t b0, b1;
                        if (p == 0) {
                            b0 = Bs[g][kb + t4][nc];
                            b1 = Bs[g][kb + t4 + 4][nc];
                        } else {
                            b0 = Bs[g][nc][kb + t4];
                            b1 = Bs[g][nc][kb + t4 + 4];
                        }
                        mma8(acc[3 * p + g] + nt * 4, a0, a1, a2, a3, b0, b1);
                    }
                }
            }
        }
    }

    // epilogue: GRU gates
#pragma unroll
    for (int nt = 0; nt < 2; nt++)
#pragma unroll
        for (int j = 0; j < 4; j++) {
            int row = i0 + wm * 16 + g8 + ((j >> 1) << 3);
            int col = c0 + wn * 16 + nt * 8 + t4 * 2 + (j & 1);
            if (row < NN) {
                int q = nt * 4 + j;
                float vr = acc[0][q] + __ldg(&bih[col])          + acc[3][q] + __ldg(&bhh[col]);
                float vz = acc[1][q] + __ldg(&bih[col + HH])     + acc[4][q] + __ldg(&bhh[col + HH]);
                float r = sigm(vr);
                float z = sigm(vz);
                float in_ = acc[2][q] + __ldg(&bih[col + 2 * HH]);
                float hn  = acc[5][q] + __ldg(&bhh[col + 2 * HH]);
                float n = tanh_fast(in_ + r * hn);
                float h = X[(size_t)row * HH + col];
                out[(size_t)row * HH + col] = (1.f - z) * n + z * h;
            }
        }
}

// ---------------- launch ----------------
extern "C" void kernel_launch(void* const* d_in, const int* in_sizes, int n_in,
                              void* d_out, int out_size) {
    const void* inputs = d_in[0];
    const void* A      = d_in[1];
    const float* emb    = (const float*)d_in[2];
    const float* weight = (const float*)d_in[3];
    const float* w_ih   = (const float*)d_in[4];
    const float* w_hh   = (const float*)d_in[5];
    const float* b_ih   = (const float*)d_in[6];
    const float* b_hh   = (const float*)d_in[7];
    float* out = (float*)d_out;

    k_detect<<<1, 128>>>((const int*)A);
    int T = 2 * NE + NN + NN + 1;
    k_prep<<<(T + 255) / 256, 256>>>(A, inputs);
    k_gx0<<<(NN * (HH / 4) + 255) / 256, 256>>>(emb);
    k_hist<<<(NE + 255) / 256, 256>>>();
    k_scan<<<1, 1024>>>();
    k_cur<<<(NN + 255) / 256, 256>>>();
    k_fill<<<(NE + 255) / 256, 256>>>();
    for (int l = 0; l < 2; l++)
        k_wp<<<dim3(G3 / 32, HH / 64), 256>>>(weight + (size_t)l * HH * HH, w_ih, l);
    for (int l = 0; l < 2; l++) {
        k_gsum<<<NN, 128>>>(l);
        k_fused<<<dim3(HH / 32, (NN + 127) / 128), 512>>>(
            l, l, (l == 1) ? 1 : 0, out, w_hh, b_ih, b_hh);
    }
}